// round 2
// baseline (speedup 1.0000x reference)
#include <cuda_runtime.h>

#define M_DIM 512
#define N_DIM 768
#define TILE  32
#define KC    32
#define SPAD  36   // padded smem row stride (floats)
#define NT    (M_DIM / TILE)   // 16

// Converted GT indices (int), per-block partials (deterministic reduction).
__device__ int   g_idx[M_DIM];
__device__ float g_partials[NT * NT];

// Detect whether GT buffer is int64 or int32, convert to int32 indices.
// Only touches the first 2048 bytes for detection (safe in both layouts),
// then reads with the detected stride (matches actual buffer size).
__global__ void prep_kernel(const int* __restrict__ gt32)
{
    __shared__ int odd_or;
    const int tid = threadIdx.x;   // 512 threads
    if (tid == 0) odd_or = 0;
    __syncthreads();

    // OR of odd words among first 512 words (2048 bytes).
    // int64 arange/small values -> all odd words 0; int32 arange -> nonzero.
    int w = gt32[tid];
    if (tid & 1) atomicOr(&odd_or, w);
    __syncthreads();

    const bool is64 = (odd_or == 0);
    g_idx[tid] = is64 ? gt32[2 * tid] : gt32[tid];
}

__device__ __forceinline__ void acc_relu_sq(float& acc, float a, float b) {
    float d = a - b;
    d = fmaxf(d, 0.0f);
    acc = fmaf(d, d, acc);
}

__global__ void __launch_bounds__(256, 1)
pair_tile_kernel(const float* __restrict__ repr)
{
    const int tj = blockIdx.x;
    const int ti = blockIdx.y;
    const int pidx = ti * NT + tj;
    const int tid = threadIdx.x;

    if (ti > tj) {  // lower-triangle tile: no pairs
        if (tid == 0) g_partials[pidx] = 0.0f;
        return;
    }

    __shared__ float As[TILE][SPAD];
    __shared__ float Bs[TILE][SPAD];

    const int tx = tid & 15;        // j sub-index
    const int ty = tid >> 4;        // i sub-index

    // Global-load mapping: 32 rows x 8 float4 per tile
    const int lrow = tid >> 3;        // 0..31
    const int lcol = (tid & 7) * 4;   // 0,4,...,28

    const int ga = g_idx[ti * TILE + lrow];
    const int gb = g_idx[tj * TILE + lrow];
    const float* arow = repr + (long)ga * N_DIM;
    const float* brow = repr + (long)gb * N_DIM;

    float acc00 = 0.0f, acc01 = 0.0f, acc10 = 0.0f, acc11 = 0.0f;

    for (int kc = 0; kc < N_DIM; kc += KC) {
        float4 av = *(const float4*)(arow + kc + lcol);
        float4 bv = *(const float4*)(brow + kc + lcol);
        __syncthreads();
        *(float4*)&As[lrow][lcol] = av;
        *(float4*)&Bs[lrow][lcol] = bv;
        __syncthreads();

        #pragma unroll
        for (int k = 0; k < KC; k += 4) {
            float4 a0 = *(const float4*)&As[ty][k];
            float4 a1 = *(const float4*)&As[ty + 16][k];
            float4 b0 = *(const float4*)&Bs[tx][k];
            float4 b1 = *(const float4*)&Bs[tx + 16][k];

            acc_relu_sq(acc00, a0.x, b0.x);
            acc_relu_sq(acc00, a0.y, b0.y);
            acc_relu_sq(acc00, a0.z, b0.z);
            acc_relu_sq(acc00, a0.w, b0.w);

            acc_relu_sq(acc01, a0.x, b1.x);
            acc_relu_sq(acc01, a0.y, b1.y);
            acc_relu_sq(acc01, a0.z, b1.z);
            acc_relu_sq(acc01, a0.w, b1.w);

            acc_relu_sq(acc10, a1.x, b0.x);
            acc_relu_sq(acc10, a1.y, b0.y);
            acc_relu_sq(acc10, a1.z, b0.z);
            acc_relu_sq(acc10, a1.w, b0.w);

            acc_relu_sq(acc11, a1.x, b1.x);
            acc_relu_sq(acc11, a1.y, b1.y);
            acc_relu_sq(acc11, a1.z, b1.z);
            acc_relu_sq(acc11, a1.w, b1.w);
        }
    }

    // Mask (global i < global j), sqrt, per-thread sum
    const int gi0 = ti * TILE + ty;
    const int gi1 = gi0 + 16;
    const int gj0 = tj * TILE + tx;
    const int gj1 = gj0 + 16;

    float v = 0.0f;
    if (gi0 < gj0) v += sqrtf(acc00);
    if (gi0 < gj1) v += sqrtf(acc01);
    if (gi1 < gj0) v += sqrtf(acc10);
    if (gi1 < gj1) v += sqrtf(acc11);

    #pragma unroll
    for (int o = 16; o > 0; o >>= 1)
        v += __shfl_xor_sync(0xffffffffu, v, o);

    __shared__ float wsum[8];
    if ((tid & 31) == 0) wsum[tid >> 5] = v;
    __syncthreads();
    if (tid == 0) {
        float s = 0.0f;
        #pragma unroll
        for (int w = 0; w < 8; w++) s += wsum[w];
        g_partials[pidx] = s;
    }
}

__global__ void reduce_kernel(float* __restrict__ out)
{
    const int tid = threadIdx.x;  // 256 threads, 256 partials
    float v = g_partials[tid];
    #pragma unroll
    for (int o = 16; o > 0; o >>= 1)
        v += __shfl_xor_sync(0xffffffffu, v, o);

    __shared__ float wsum[8];
    if ((tid & 31) == 0) wsum[tid >> 5] = v;
    __syncthreads();
    if (tid == 0) {
        float s = 0.0f;
        #pragma unroll
        for (int w = 0; w < 8; w++) s += wsum[w];
        *out = s;
    }
}

extern "C" void kernel_launch(void* const* d_in, const int* in_sizes, int n_in,
                              void* d_out, int out_size)
{
    const float* repr = (const float*)d_in[0];
    const int*   gt32 = (const int*)d_in[1];
    float*       out  = (float*)d_out;

    prep_kernel<<<1, M_DIM>>>(gt32);
    dim3 grid(NT, NT);
    pair_tile_kernel<<<grid, 256>>>(repr);
    reduce_kernel<<<1, 256>>>(out);
}

// round 5
// speedup vs baseline: 1.3876x; 1.3876x over previous
#include <cuda_runtime.h>
#include <cstdint>

#define M_DIM  512
#define N_DIM  768
#define BT     64            // pair-tile side
#define NTT    8             // tiles per dimension (512/64)
#define NTILES 36            // upper-triangular tile pairs (8*9/2)
#define NSLICE 4             // K splits
#define KS     192           // k's per slice (768/4)
#define KC     32            // k's per smem chunk
#define SPAD   36            // smem row stride (floats): 4 mod 32 -> conflict-free b-loads

// Scratch: per-(slice,tile) 64x64 partial sum-of-squares. 2.36 MB.
__device__ float g_sumsq[NSLICE * NTILES * BT * BT];
__device__ float g_partials[NTILES];
__device__ int   g_done;

__device__ __forceinline__ uint64_t pk2(float x, float y) {
    uint64_t r;
    asm("mov.b64 %0, {%1, %2};" : "=l"(r) : "f"(x), "f"(y));
    return r;
}

__device__ __forceinline__ float hsum2(uint64_t v) {
    float lo, hi;
    asm("mov.b64 {%0, %1}, %2;" : "=f"(lo), "=f"(hi) : "l"(v));
    return lo + hi;
}

// acc2 += d * relu(d)  (== relu(d)^2), d = a + (-b), two k's packed per op.
// Packed add/fma on fma pipe (1 op / 2 elems); relu on alu pipe (FMNMX).
__device__ __forceinline__ void step2(uint64_t& acc, uint64_t a2, uint64_t nb2) {
    asm("{\n\t"
        ".reg .b64 d2, r2;\n\t"
        ".reg .f32 lo, hi;\n\t"
        "add.rn.f32x2 d2, %1, %2;\n\t"
        "mov.b64 {lo, hi}, d2;\n\t"
        "max.f32 lo, lo, 0f00000000;\n\t"
        "max.f32 hi, hi, 0f00000000;\n\t"
        "mov.b64 r2, {lo, hi};\n\t"
        "fma.rn.f32x2 %0, d2, r2, %0;\n\t"
        "}" : "+l"(acc) : "l"(a2), "l"(nb2));
}

__device__ __forceinline__ void unrank_tile(int t, int& ti, int& tj) {
    int r = t; ti = 0;
    while (r >= NTT - ti) { r -= NTT - ti; ti++; }
    tj = ti + r;
}

__global__ void __launch_bounds__(256, 1)
pass1_kernel(const float* __restrict__ repr, const int* __restrict__ gt32)
{
    __shared__ float As[BT][SPAD];
    __shared__ float Bs[BT][SPAD];   // negated
    __shared__ int   iIdx[BT], jIdx[BT];
    __shared__ int   odd_or;

    const int tid = threadIdx.x;
    const int b   = blockIdx.x;
    const int t   = b % NTILES;
    const int s   = b / NTILES;
    int ti, tj;
    unrank_tile(t, ti, tj);

    // --- GT dtype detection (only first 2048 bytes touched: safe either way) ---
    if (tid == 0) odd_or = 0;
    __syncthreads();
    atomicOr(&odd_or, gt32[2 * tid + 1]);   // odd words: 0 iff int64 small values
    __syncthreads();
    const bool is64 = (odd_or == 0);
    if (tid < BT) {
        int gr = ti * BT + tid;
        iIdx[tid] = is64 ? gt32[2 * gr] : gt32[gr];
    } else if (tid < 2 * BT) {
        int r  = tid - BT;
        int gr = tj * BT + r;
        jIdx[r] = is64 ? gt32[2 * gr] : gt32[gr];
    }
    __syncthreads();

    // --- staging mapping: 64 rows x 8 float4 per chunk; 256 thr -> 2 f4 each ---
    const int lrow = tid >> 2;          // 0..63
    const int lc   = (tid & 3) * 4;     // float col 0,4,8,12 (and +16)
    const float* ap = repr + (long)iIdx[lrow] * N_DIM + s * KS + lc;
    const float* bp = repr + (long)jIdx[lrow] * N_DIM + s * KS + lc;

    const int tx = tid & 15;            // j sub-index (cols tx + 16c)
    const int ty = tid >> 4;            // i sub-index (rows ty + 16r)

    uint64_t acc[4][4];
    #pragma unroll
    for (int r = 0; r < 4; r++)
        #pragma unroll
        for (int c = 0; c < 4; c++) acc[r][c] = 0ull;

    for (int ch = 0; ch < KS / KC; ch++) {
        float4 a0 = *(const float4*)(ap);
        float4 a1 = *(const float4*)(ap + 16);
        float4 b0 = *(const float4*)(bp);
        float4 b1 = *(const float4*)(bp + 16);
        ap += KC; bp += KC;

        __syncthreads();   // prior chunk fully consumed
        *(float4*)&As[lrow][lc]      = a0;
        *(float4*)&As[lrow][lc + 16] = a1;
        b0.x = -b0.x; b0.y = -b0.y; b0.z = -b0.z; b0.w = -b0.w;
        b1.x = -b1.x; b1.y = -b1.y; b1.z = -b1.z; b1.w = -b1.w;
        *(float4*)&Bs[lrow][lc]      = b0;
        *(float4*)&Bs[lrow][lc + 16] = b1;
        __syncthreads();

        #pragma unroll
        for (int kq = 0; kq < KC / 4; kq++) {
            float4 av[4], bv[4];
            #pragma unroll
            for (int r = 0; r < 4; r++)
                av[r] = *(const float4*)&As[ty + 16 * r][kq * 4];
            #pragma unroll
            for (int c = 0; c < 4; c++)
                bv[c] = *(const float4*)&Bs[tx + 16 * c][kq * 4];

            #pragma unroll
            for (int r = 0; r < 4; r++) {
                #pragma unroll
                for (int c = 0; c < 4; c++) {
                    step2(acc[r][c], pk2(av[r].x, av[r].y), pk2(bv[c].x, bv[c].y));
                    step2(acc[r][c], pk2(av[r].z, av[r].w), pk2(bv[c].z, bv[c].w));
                }
            }
        }
    }

    // --- write 16 partial sumsq values to scratch ---
    float* dst = g_sumsq + (s * NTILES + t) * (BT * BT);
    #pragma unroll
    for (int r = 0; r < 4; r++)
        #pragma unroll
        for (int c = 0; c < 4; c++)
            dst[(ty + 16 * r) * BT + (tx + 16 * c)] = hsum2(acc[r][c]);
}

__global__ void __launch_bounds__(256, 1)
pass2_kernel(float* __restrict__ out)
{
    const int tid = threadIdx.x;
    const int t   = blockIdx.x;
    int ti, tj;
    unrank_tile(t, ti, tj);

    float v = 0.0f;
    #pragma unroll
    for (int p = tid; p < BT * BT; p += 256) {
        float ssum = 0.0f;
        #pragma unroll
        for (int s = 0; s < NSLICE; s++)
            ssum += g_sumsq[(s * NTILES + t) * (BT * BT) + p];
        int gi = ti * BT + (p >> 6);
        int gj = tj * BT + (p & 63);
        if (gi < gj) v += sqrtf(ssum);
    }

    #pragma unroll
    for (int o = 16; o > 0; o >>= 1)
        v += __shfl_xor_sync(0xffffffffu, v, o);

    __shared__ float wsum[8];
    if ((tid & 31) == 0) wsum[tid >> 5] = v;
    __syncthreads();

    if (tid == 0) {
        float blocksum = 0.0f;
        #pragma unroll
        for (int w = 0; w < 8; w++) blocksum += wsum[w];
        g_partials[t] = blocksum;
        __threadfence();
        if (atomicAdd(&g_done, 1) == NTILES - 1) {
            volatile float* gp = g_partials;
            float total = 0.0f;
            for (int i = 0; i < NTILES; i++) total += gp[i];
            *out = total;
            g_done = 0;    // reset for next graph replay
        }
    }
}

extern "C" void kernel_launch(void* const* d_in, const int* in_sizes, int n_in,
                              void* d_out, int out_size)
{
    const float* repr = (const float*)d_in[0];
    const int*   gt32 = (const int*)d_in[1];
    float*       out  = (float*)d_out;

    pass1_kernel<<<NTILES * NSLICE, 256>>>(repr, gt32);
    pass2_kernel<<<NTILES, 256>>>(out);
}